// round 16
// baseline (speedup 1.0000x reference)
#include <cuda_runtime.h>
#include <cuda_fp16.h>
#include <math.h>
#include <stdint.h>

#define N_NODES 100000
#define N_EDGES 640000
#define DIM     128
#define N_GRAPHS 512

#define SCAN_CHUNK 512
#define NB ((N_NODES + SCAN_CHUNK - 1) / SCAN_CHUNK)   // 196
#define PBLOCKS ((N_NODES * 32 + 255) / 256)           // 12500
#define WBLOCKS 64                                     // w12 tail: 2 rows/block
#define CPBLOCKS 1850                                  // cprop grid (grid-stride)
#define CPWARPS (CPBLOCKS * 8)                         // 14800 warps

// ---------------- device scratch (allocation-free) ----------------
__device__ __half g_hx[(size_t)N_NODES * DIM];   // fp16 copy of x
__device__ __half g_h1[(size_t)N_NODES * DIM];   // y1 / y3
__device__ __half g_h2[(size_t)N_NODES * DIM];   // y2
__device__ float g_dinv[N_NODES];
__device__ int   g_deg[N_NODES];
__device__ int   g_ptr[N_NODES + 1];
__device__ int   g_cur[N_NODES];
__device__ int2  g_edge[N_EDGES];                // {row, bits(norm)}, CSR order
__device__ int   g_flag[NB];                     // look-back: 0/1(agg)/2(inc)
__device__ int   g_agg[NB];
__device__ int   g_inc[NB];
__device__ __half g_BhT[DIM * DIM];              // W12^T in fp16: [n][k]
__device__ float g_z[N_GRAPHS * DIM];

// ------- prep (stream B): x -> fp16, zero z; tail blocks do W12^T -----
__global__ void __launch_bounds__(256) k_prep(const float* __restrict__ x,
                                              const float* __restrict__ W0,
                                              const float* __restrict__ W1) {
    int b = blockIdx.x;
    if (b < PBLOCKS) {
        int i = b * blockDim.x + threadIdx.x;        // one float4 slot
        if (i < N_NODES * 32) {
            float4 v = *reinterpret_cast<const float4*>(x + (size_t)i * 4);
            __half2 h0 = __floats2half2_rn(v.x, v.y);
            __half2 h1 = __floats2half2_rn(v.z, v.w);
            uint2 u;
            u.x = *reinterpret_cast<uint32_t*>(&h0);
            u.y = *reinterpret_cast<uint32_t*>(&h1);
            *reinterpret_cast<uint2*>(&g_hx[(size_t)i * 4]) = u;
        }
        if (i < N_GRAPHS * DIM) g_z[i] = 0.f;        // z used only by cprop<2>
        return;
    }
    // ---- W12 = W0 @ W1, store transposed fp16: 2 weight-rows per block
    __shared__ float sw0[2][DIM];
    int wb = b - PBLOCKS;                  // 0..63
    int half = threadIdx.x >> 7;           // 0/1
    int j = threadIdx.x & 127;
    int i = wb * 2 + half;                 // weight row (k index) 0..127
    sw0[half][j] = W0[i * DIM + j];
    __syncthreads();
    float a0 = 0.f, a1 = 0.f, a2 = 0.f, a3 = 0.f;
    #pragma unroll
    for (int k = 0; k < DIM; k += 4) {
        a0 += sw0[half][k + 0] * W1[(k + 0) * DIM + j];
        a1 += sw0[half][k + 1] * W1[(k + 1) * DIM + j];
        a2 += sw0[half][k + 2] * W1[(k + 2) * DIM + j];
        a3 += sw0[half][k + 3] * W1[(k + 3) * DIM + j];
    }
    float acc = (a0 + a1) + (a2 + a3);
    g_BhT[j * DIM + i] = __float2half_rn(acc);   // B^T[n=j][k=i]
}

// ------- zero (stream A): deg + look-back flags ------------------------
__global__ void k_zero() {
    int i = blockIdx.x * blockDim.x + threadIdx.x;
    if (i < N_NODES) g_deg[i] = 0;
    if (i < NB) g_flag[i] = 0;
}

// ---------------- degree histogram (node counters only) --------------
__global__ void k_deg(const int* __restrict__ col) {
    int e = blockIdx.x * blockDim.x + threadIdx.x;
    if (e < N_EDGES) atomicAdd(&g_deg[col[e]], 1);
}

// ------- single-pass scan (decoupled look-back): dinv + ptr/cur -------
__global__ void __launch_bounds__(SCAN_CHUNK) k_scan() {
    __shared__ int s[SCAN_CHUNK];
    __shared__ int s_boff;
    int b = blockIdx.x, t = threadIdx.x;

    int v = b * SCAN_CHUNK + t;
    int cnt = 0;
    if (v < N_NODES) {
        cnt = g_deg[v];
        g_dinv[v] = rsqrtf((float)(cnt + 1));   // +1 self loop
    }
    s[t] = cnt;
    __syncthreads();
    for (int off = 1; off < SCAN_CHUNK; off <<= 1) {
        int tmp = (t >= off) ? s[t - off] : 0;
        __syncthreads();
        s[t] += tmp;
        __syncthreads();
    }

    if (t == 0) {
        int total = s[SCAN_CHUNK - 1];
        g_agg[b] = total;
        __threadfence();
        atomicExch(&g_flag[b], 1);

        int prefix = 0;
        if (b > 0) {
            int p = b - 1;
            while (true) {
                int f;
                do { f = atomicAdd(&g_flag[p], 0); } while (f == 0);
                if (f == 2) { prefix += atomicAdd(&g_inc[p], 0); break; }
                prefix += atomicAdd(&g_agg[p], 0);
                if (p == 0) break;
                p--;
            }
        }
        g_inc[b] = prefix + total;
        __threadfence();
        atomicExch(&g_flag[b], 2);
        s_boff = prefix;
    }
    __syncthreads();
    int boff = s_boff;

    if (v < N_NODES) {
        int incl = s[t];
        int p = boff + incl - cnt;
        g_ptr[v] = p;
        g_cur[v] = p;
        if (v == N_NODES - 1) g_ptr[N_NODES] = boff + incl;
    }
}

// ---------------- scatter edges into CSR (packed row+norm) ------------
__global__ void k_scatter(const int* __restrict__ row,
                          const int* __restrict__ col) {
    int e = blockIdx.x * blockDim.x + threadIdx.x;
    if (e < N_EDGES) {
        int r = row[e];
        int c = col[e];
        int pos = atomicAdd(&g_cur[c], 1);
        float nrm = g_dinv[r] * g_dinv[c];
        g_edge[pos] = make_int2(r, __float_as_int(nrm));
    }
}

// ---------------- fp16 gather helper (plain loads) ----------------
__device__ __forceinline__ float4 ld_row_h4(const __half* src, int r, int lane) {
    uint2 u = *reinterpret_cast<const uint2*>(src + (size_t)r * DIM + lane * 4);
    __half2 h0 = *reinterpret_cast<__half2*>(&u.x);
    __half2 h1 = *reinterpret_cast<__half2*>(&u.y);
    float2 f0 = __half22float2(h0);
    float2 f1 = __half22float2(h1);
    return make_float4(f0.x, f0.y, f1.x, f1.y);
}

// ------- CSR propagation: grid-stride warp per node, MLP-4 loop -------
// MODE 0: src = g_hx -> g_h1
// MODE 1: src = g_h1 -> g_h2
// MODE 2: src = g_h1 -> red.add into g_z[batch[v]]  (fp32)
template <int MODE>
__global__ void __launch_bounds__(256) k_cprop(const int* __restrict__ batch) {
    int warp0 = (blockIdx.x * blockDim.x + threadIdx.x) >> 5;
    int lane = threadIdx.x & 31;
    const __half* src = (MODE == 0) ? g_hx : g_h1;

    for (int gw = warp0; gw < N_NODES; gw += CPWARPS) {
        float dv = g_dinv[gw];

        float4 a = ld_row_h4(src, gw, lane);
        float s = dv * dv;
        float4 acc = make_float4(a.x * s, a.y * s, a.z * s, a.w * s);

        int beg = g_ptr[gw], end = g_ptr[gw + 1];
        for (int base = beg; base < end; base += 32) {
            int idx = base + lane;
            int r = 0;
            float nrm = 0.f;
            if (idx < end) {
                int2 e = g_edge[idx];
                r = e.x;
                nrm = __int_as_float(e.y);
            }
            int cnt = min(32, end - base);
            int last = cnt - 1;
            for (int i = 0; i < cnt; i += 4) {
                int c1 = min(i + 1, last);
                int c2 = min(i + 2, last);
                int c3 = min(i + 3, last);
                int r0 = __shfl_sync(0xffffffffu, r, i);
                int r1 = __shfl_sync(0xffffffffu, r, c1);
                int r2 = __shfl_sync(0xffffffffu, r, c2);
                int r3 = __shfl_sync(0xffffffffu, r, c3);
                float n0 = __shfl_sync(0xffffffffu, nrm, i);
                float n1 = __shfl_sync(0xffffffffu, nrm, c1);
                float n2 = __shfl_sync(0xffffffffu, nrm, c2);
                float n3 = __shfl_sync(0xffffffffu, nrm, c3);
                n1 = (i + 1 < cnt) ? n1 : 0.f;
                n2 = (i + 2 < cnt) ? n2 : 0.f;
                n3 = (i + 3 < cnt) ? n3 : 0.f;
                float4 x0 = ld_row_h4(src, r0, lane);
                float4 x1 = ld_row_h4(src, r1, lane);
                float4 x2 = ld_row_h4(src, r2, lane);
                float4 x3 = ld_row_h4(src, r3, lane);
                acc.x += n0 * x0.x; acc.y += n0 * x0.y;
                acc.z += n0 * x0.z; acc.w += n0 * x0.w;
                acc.x += n1 * x1.x; acc.y += n1 * x1.y;
                acc.z += n1 * x1.z; acc.w += n1 * x1.w;
                acc.x += n2 * x2.x; acc.y += n2 * x2.y;
                acc.z += n2 * x2.z; acc.w += n2 * x2.w;
                acc.x += n3 * x3.x; acc.y += n3 * x3.y;
                acc.z += n3 * x3.z; acc.w += n3 * x3.w;
            }
        }

        if (MODE == 2) {
            float* dst = g_z + (size_t)batch[gw] * DIM + lane * 4;
            asm volatile("red.global.add.v4.f32 [%0], {%1, %2, %3, %4};"
                         :: "l"(dst), "f"(acc.x), "f"(acc.y), "f"(acc.z),
                            "f"(acc.w) : "memory");
        } else {
            __half* dstb = (MODE == 0) ? g_h1 : g_h2;
            __half2 o0 = __floats2half2_rn(acc.x, acc.y);
            __half2 o1 = __floats2half2_rn(acc.z, acc.w);
            uint2 u;
            u.x = *reinterpret_cast<uint32_t*>(&o0);
            u.y = *reinterpret_cast<uint32_t*>(&o1);
            *reinterpret_cast<uint2*>(dstb + (size_t)gw * DIM + lane * 4) = u;
        }
    }
}

// ---------------- y3 = leaky_relu(y2 @ W12) -> g_h1 (fp16 MMA) --------
#define KST 64
#define SST 72   // halves per row: conflict-free frag loads

__device__ __forceinline__ void mma_f16(float* c, const uint32_t* a,
                                        const uint32_t* b) {
    asm volatile(
        "mma.sync.aligned.m16n8k16.row.col.f32.f16.f16.f32 "
        "{%0,%1,%2,%3}, {%4,%5,%6,%7}, {%8,%9}, {%0,%1,%2,%3};"
        : "+f"(c[0]), "+f"(c[1]), "+f"(c[2]), "+f"(c[3])
        : "r"(a[0]), "r"(a[1]), "r"(a[2]), "r"(a[3]), "r"(b[0]), "r"(b[1]));
}

__global__ void __launch_bounds__(256) k_gemm_tc() {
    __shared__ __half sA[128 * SST];   // A tile: [row][k]  (128 x 64)
    __shared__ __half sB[128 * SST];   // B^T tile: [n][k]  (128 x 64)

    int t = threadIdx.x;
    int warp = t >> 5, lane = t & 31;
    int wm = warp >> 2, wn = warp & 3;
    int group = lane >> 2, tg = lane & 3;
    int i0 = blockIdx.x * 128;

    float acc[4][4][4];
    #pragma unroll
    for (int a = 0; a < 4; a++)
        #pragma unroll
        for (int b = 0; b < 4; b++)
            #pragma unroll
            for (int c = 0; c < 4; c++) acc[a][b][c] = 0.f;

    for (int k0 = 0; k0 < DIM; k0 += KST) {
        #pragma unroll
        for (int l = 0; l < 4; l++) {
            int q = t + l * 256;          // 0..1023
            int rrow = q >> 3;
            int c8 = (q & 7) * 8;
            uint4 v = make_uint4(0u, 0u, 0u, 0u);
            int gr = i0 + rrow;
            if (gr < N_NODES)
                v = *reinterpret_cast<const uint4*>(
                        &g_h2[(size_t)gr * DIM + k0 + c8]);
            *reinterpret_cast<uint4*>(&sA[rrow * SST + c8]) = v;
        }
        #pragma unroll
        for (int l = 0; l < 4; l++) {
            int q = t + l * 256;
            int nrow = q >> 3;
            int c8 = (q & 7) * 8;
            *reinterpret_cast<uint4*>(&sB[nrow * SST + c8]) =
                *reinterpret_cast<const uint4*>(&g_BhT[nrow * DIM + k0 + c8]);
        }
        __syncthreads();

        #pragma unroll
        for (int ks = 0; ks < KST / 16; ks++) {
            int kb = ks * 16;
            uint32_t bf[4][2];
            #pragma unroll
            for (int nn = 0; nn < 4; nn++) {
                int n0 = wn * 32 + nn * 8 + group;
                bf[nn][0] = *reinterpret_cast<const uint32_t*>(
                                &sB[n0 * SST + kb + tg * 2]);
                bf[nn][1] = *reinterpret_cast<const uint32_t*>(
                                &sB[n0 * SST + kb + 8 + tg * 2]);
            }
            uint32_t af[4][4];
            #pragma unroll
            for (int mm = 0; mm < 4; mm++) {
                int r0 = wm * 64 + mm * 16 + group;
                af[mm][0] = *reinterpret_cast<const uint32_t*>(
                                &sA[r0 * SST + kb + tg * 2]);
                af[mm][1] = *reinterpret_cast<const uint32_t*>(
                                &sA[(r0 + 8) * SST + kb + tg * 2]);
                af[mm][2] = *reinterpret_cast<const uint32_t*>(
                                &sA[r0 * SST + kb + 8 + tg * 2]);
                af[mm][3] = *reinterpret_cast<const uint32_t*>(
                                &sA[(r0 + 8) * SST + kb + 8 + tg * 2]);
            }
            #pragma unroll
            for (int mm = 0; mm < 4; mm++)
                #pragma unroll
                for (int nn = 0; nn < 4; nn++)
                    mma_f16(acc[mm][nn], af[mm], bf[nn]);
        }
        __syncthreads();
    }

    #pragma unroll
    for (int mm = 0; mm < 4; mm++) {
        #pragma unroll
        for (int nn = 0; nn < 4; nn++) {
            int colb = wn * 32 + nn * 8 + tg * 2;
            #pragma unroll
            for (int half = 0; half < 2; half++) {
                int rr = i0 + wm * 64 + mm * 16 + group + half * 8;
                if (rr < N_NODES) {
                    float v0 = acc[mm][nn][half * 2 + 0];
                    float v1 = acc[mm][nn][half * 2 + 1];
                    v0 = (v0 > 0.f) ? v0 : 0.01f * v0;
                    v1 = (v1 > 0.f) ? v1 : 0.01f * v1;
                    __half2 hv = __floats2half2_rn(v0, v1);
                    *reinterpret_cast<__half2*>(
                        &g_h1[(size_t)rr * DIM + colb]) = hv;
                }
            }
        }
    }
}

// ---------------- out = g_z @ W2 (fp32) ----------------
__global__ void k_out(const float* __restrict__ W2, float* __restrict__ out) {
    __shared__ float sz[DIM];
    int g = blockIdx.x;
    int j = threadIdx.x;
    sz[j] = g_z[g * DIM + j];
    __syncthreads();
    float acc = 0.f;
    #pragma unroll 8
    for (int k = 0; k < DIM; k++)
        acc += sz[k] * W2[k * DIM + j];
    out[g * DIM + j] = acc;
}

// ---------------- launch (fork-join: prep overlaps CSR build) ---------
extern "C" void kernel_launch(void* const* d_in, const int* in_sizes, int n_in,
                              void* d_out, int out_size) {
    const float* x     = (const float*)d_in[0];
    const int*   ei    = (const int*)d_in[1];
    const int*   batch = (const int*)d_in[2];
    const float* W0    = (const float*)d_in[3];
    const float* W1    = (const float*)d_in[4];
    const float* W2    = (const float*)d_in[5];
    float* out = (float*)d_out;

    const int* row = ei;
    const int* col = ei + N_EDGES;

    cudaStream_t s2;
    cudaStreamCreateWithFlags(&s2, cudaStreamNonBlocking);
    cudaEvent_t eFork, eJoin;
    cudaEventCreateWithFlags(&eFork, cudaEventDisableTiming);
    cudaEventCreateWithFlags(&eJoin, cudaEventDisableTiming);

    cudaEventRecord(eFork, 0);
    cudaStreamWaitEvent(s2, eFork, 0);

    // branch B (s2): x -> fp16 + W12^T fp16 + zero z
    k_prep<<<PBLOCKS + WBLOCKS, 256, 0, s2>>>(x, W0, W1);
    cudaEventRecord(eJoin, s2);

    // branch A (stream 0): CSR build
    k_zero<<<(N_NODES + 255) / 256, 256>>>();
    k_deg<<<(N_EDGES + 255) / 256, 256>>>(col);
    k_scan<<<NB, SCAN_CHUNK>>>();
    k_scatter<<<(N_EDGES + 255) / 256, 256>>>(row, col);

    cudaStreamWaitEvent(0, eJoin, 0);

    k_cprop<0><<<CPBLOCKS, 256>>>(batch);            // y1 = Â x      (fp16)
    k_cprop<1><<<CPBLOCKS, 256>>>(batch);            // y2 = Â y1     (fp16)
    k_gemm_tc<<<(N_NODES + 127) / 128, 256>>>();     // y3 = leaky(y2@W12)
    k_cprop<2><<<CPBLOCKS, 256>>>(batch);            // z = P Â y3    (fp32)
    k_out<<<N_GRAPHS, DIM>>>(W2, out);
}

// round 17
// speedup vs baseline: 1.1034x; 1.1034x over previous
#include <cuda_runtime.h>
#include <cuda_fp16.h>
#include <math.h>
#include <stdint.h>

#define N_NODES 100000
#define N_EDGES 640000
#define DIM     128
#define N_GRAPHS 512

#define SCAN_CHUNK 512
#define NB ((N_NODES + SCAN_CHUNK - 1) / SCAN_CHUNK)   // 196
#define PBLOCKS ((N_NODES * 32 + 255) / 256)           // 12500
#define WBLOCKS 64                                     // w12 tail: 2 rows/block
#define CPBLOCKS 1850                                  // cprop grid (grid-stride)
#define CPWARPS (CPBLOCKS * 8)                         // 14800 warps

// ---------------- device scratch (allocation-free) ----------------
__device__ __half g_hx[(size_t)N_NODES * DIM];   // fp16 copy of x
__device__ __half g_h1[(size_t)N_NODES * DIM];   // y1 / y3
__device__ __half g_h2[(size_t)N_NODES * DIM];   // y2
__device__ float g_dinv[N_NODES];
__device__ int   g_deg[N_NODES];
__device__ int   g_ptr[N_NODES + 1];
__device__ int   g_cur[N_NODES];
__device__ int2  g_edge[N_EDGES];                // {row, bits(norm)}, CSR order
__device__ int   g_bsum[NB];
__device__ __half g_BhT[DIM * DIM];              // W12^T in fp16: [n][k]
__device__ float g_z[N_GRAPHS * DIM];

// ------- prep (stream B): x -> fp16, zero z; tail blocks do W12^T -----
__global__ void __launch_bounds__(256) k_prep(const float* __restrict__ x,
                                              const float* __restrict__ W0,
                                              const float* __restrict__ W1) {
    int b = blockIdx.x;
    if (b < PBLOCKS) {
        int i = b * blockDim.x + threadIdx.x;        // one float4 slot
        if (i < N_NODES * 32) {
            float4 v = *reinterpret_cast<const float4*>(x + (size_t)i * 4);
            __half2 h0 = __floats2half2_rn(v.x, v.y);
            __half2 h1 = __floats2half2_rn(v.z, v.w);
            uint2 u;
            u.x = *reinterpret_cast<uint32_t*>(&h0);
            u.y = *reinterpret_cast<uint32_t*>(&h1);
            *reinterpret_cast<uint2*>(&g_hx[(size_t)i * 4]) = u;
        }
        if (i < N_GRAPHS * DIM) g_z[i] = 0.f;        // z used only by cprop<2>
        return;
    }
    // ---- W12 = W0 @ W1, store transposed fp16: 2 weight-rows per block
    __shared__ float sw0[2][DIM];
    int wb = b - PBLOCKS;                  // 0..63
    int half = threadIdx.x >> 7;           // 0/1
    int j = threadIdx.x & 127;
    int i = wb * 2 + half;                 // weight row (k index) 0..127
    sw0[half][j] = W0[i * DIM + j];
    __syncthreads();
    float a0 = 0.f, a1 = 0.f, a2 = 0.f, a3 = 0.f;
    #pragma unroll
    for (int k = 0; k < DIM; k += 4) {
        a0 += sw0[half][k + 0] * W1[(k + 0) * DIM + j];
        a1 += sw0[half][k + 1] * W1[(k + 1) * DIM + j];
        a2 += sw0[half][k + 2] * W1[(k + 2) * DIM + j];
        a3 += sw0[half][k + 3] * W1[(k + 3) * DIM + j];
    }
    float acc = (a0 + a1) + (a2 + a3);
    g_BhT[j * DIM + i] = __float2half_rn(acc);   // B^T[n=j][k=i]
}

// ------- zero (stream A): deg only ------------------------------------
__global__ void k_zero() {
    int i = blockIdx.x * blockDim.x + threadIdx.x;
    if (i < N_NODES) g_deg[i] = 0;
}

// ---------------- degree histogram (node counters only) --------------
__global__ void k_deg(const int* __restrict__ col) {
    int e = blockIdx.x * blockDim.x + threadIdx.x;
    if (e < N_EDGES) atomicAdd(&g_deg[col[e]], 1);
}

// ---------------- scan pass 1: per-chunk sums + dinv ----------------
__global__ void __launch_bounds__(256) k_scan1() {
    __shared__ int s[256];
    int b = blockIdx.x, t = threadIdx.x;
    int sum = 0;
    #pragma unroll
    for (int l = 0; l < 2; l++) {
        int v = b * SCAN_CHUNK + t + l * 256;
        if (v < N_NODES) {
            int d = g_deg[v];
            g_dinv[v] = rsqrtf((float)(d + 1));   // +1 self loop
            sum += d;
        }
    }
    s[t] = sum;
    __syncthreads();
    for (int off = 128; off > 0; off >>= 1) {
        if (t < off) s[t] += s[t + off];
        __syncthreads();
    }
    if (t == 0) g_bsum[b] = s[0];
}

// ---------------- scan pass 2 (fused): ptr / cur ----------------
__global__ void __launch_bounds__(SCAN_CHUNK) k_scan3() {
    __shared__ int s[SCAN_CHUNK];
    __shared__ int sb[256];
    int t = threadIdx.x;

    if (t < 256) sb[t] = (t < NB) ? g_bsum[t] : 0;
    __syncthreads();
    for (int off = 1; off < 256; off <<= 1) {
        int tmp = (t < 256 && t >= off) ? sb[t - off] : 0;
        __syncthreads();
        if (t < 256) sb[t] += tmp;
        __syncthreads();
    }
    int boff = (blockIdx.x == 0) ? 0 : sb[blockIdx.x - 1];

    int v = blockIdx.x * SCAN_CHUNK + t;
    int cnt = (v < N_NODES) ? g_deg[v] : 0;
    s[t] = cnt;
    __syncthreads();
    for (int off = 1; off < SCAN_CHUNK; off <<= 1) {
        int tmp = (t >= off) ? s[t - off] : 0;
        __syncthreads();
        s[t] += tmp;
        __syncthreads();
    }
    if (v < N_NODES) {
        int incl = s[t];
        int p = boff + incl - cnt;
        g_ptr[v] = p;
        g_cur[v] = p;
        if (v == N_NODES - 1) g_ptr[N_NODES] = boff + incl;
    }
}

// ---------------- scatter edges into CSR (packed row+norm) ------------
__global__ void k_scatter(const int* __restrict__ row,
                          const int* __restrict__ col) {
    int e = blockIdx.x * blockDim.x + threadIdx.x;
    if (e < N_EDGES) {
        int r = row[e];
        int c = col[e];
        int pos = atomicAdd(&g_cur[c], 1);
        float nrm = g_dinv[r] * g_dinv[c];
        g_edge[pos] = make_int2(r, __float_as_int(nrm));
    }
}

// ---------------- fp16 gather helper (plain loads) ----------------
__device__ __forceinline__ float4 ld_row_h4(const __half* src, int r, int lane) {
    uint2 u = *reinterpret_cast<const uint2*>(src + (size_t)r * DIM + lane * 4);
    __half2 h0 = *reinterpret_cast<__half2*>(&u.x);
    __half2 h1 = *reinterpret_cast<__half2*>(&u.y);
    float2 f0 = __half22float2(h0);
    float2 f1 = __half22float2(h1);
    return make_float4(f0.x, f0.y, f1.x, f1.y);
}

// ------- CSR propagation: grid-stride warp per node, MLP-4 loop -------
// MODE 0: src = g_hx -> g_h1
// MODE 1: src = g_h1 -> g_h2
// MODE 2: src = g_h1 -> red.add into g_z[batch[v]]  (fp32)
template <int MODE>
__global__ void __launch_bounds__(256) k_cprop(const int* __restrict__ batch) {
    int warp0 = (blockIdx.x * blockDim.x + threadIdx.x) >> 5;
    int lane = threadIdx.x & 31;
    const __half* src = (MODE == 0) ? g_hx : g_h1;

    for (int gw = warp0; gw < N_NODES; gw += CPWARPS) {
        float dv = g_dinv[gw];

        float4 a = ld_row_h4(src, gw, lane);
        float s = dv * dv;
        float4 acc = make_float4(a.x * s, a.y * s, a.z * s, a.w * s);

        int beg = g_ptr[gw], end = g_ptr[gw + 1];
        for (int base = beg; base < end; base += 32) {
            int idx = base + lane;
            int r = 0;
            float nrm = 0.f;
            if (idx < end) {
                int2 e = g_edge[idx];
                r = e.x;
                nrm = __int_as_float(e.y);
            }
            int cnt = min(32, end - base);
            int last = cnt - 1;
            for (int i = 0; i < cnt; i += 4) {
                int c1 = min(i + 1, last);
                int c2 = min(i + 2, last);
                int c3 = min(i + 3, last);
                int r0 = __shfl_sync(0xffffffffu, r, i);
                int r1 = __shfl_sync(0xffffffffu, r, c1);
                int r2 = __shfl_sync(0xffffffffu, r, c2);
                int r3 = __shfl_sync(0xffffffffu, r, c3);
                float n0 = __shfl_sync(0xffffffffu, nrm, i);
                float n1 = __shfl_sync(0xffffffffu, nrm, c1);
                float n2 = __shfl_sync(0xffffffffu, nrm, c2);
                float n3 = __shfl_sync(0xffffffffu, nrm, c3);
                n1 = (i + 1 < cnt) ? n1 : 0.f;
                n2 = (i + 2 < cnt) ? n2 : 0.f;
                n3 = (i + 3 < cnt) ? n3 : 0.f;
                float4 x0 = ld_row_h4(src, r0, lane);
                float4 x1 = ld_row_h4(src, r1, lane);
                float4 x2 = ld_row_h4(src, r2, lane);
                float4 x3 = ld_row_h4(src, r3, lane);
                acc.x += n0 * x0.x; acc.y += n0 * x0.y;
                acc.z += n0 * x0.z; acc.w += n0 * x0.w;
                acc.x += n1 * x1.x; acc.y += n1 * x1.y;
                acc.z += n1 * x1.z; acc.w += n1 * x1.w;
                acc.x += n2 * x2.x; acc.y += n2 * x2.y;
                acc.z += n2 * x2.z; acc.w += n2 * x2.w;
                acc.x += n3 * x3.x; acc.y += n3 * x3.y;
                acc.z += n3 * x3.z; acc.w += n3 * x3.w;
            }
        }

        if (MODE == 2) {
            float* dst = g_z + (size_t)batch[gw] * DIM + lane * 4;
            asm volatile("red.global.add.v4.f32 [%0], {%1, %2, %3, %4};"
                         :: "l"(dst), "f"(acc.x), "f"(acc.y), "f"(acc.z),
                            "f"(acc.w) : "memory");
        } else {
            __half* dstb = (MODE == 0) ? g_h1 : g_h2;
            __half2 o0 = __floats2half2_rn(acc.x, acc.y);
            __half2 o1 = __floats2half2_rn(acc.z, acc.w);
            uint2 u;
            u.x = *reinterpret_cast<uint32_t*>(&o0);
            u.y = *reinterpret_cast<uint32_t*>(&o1);
            *reinterpret_cast<uint2*>(dstb + (size_t)gw * DIM + lane * 4) = u;
        }
    }
}

// ---------------- y3 = leaky_relu(y2 @ W12) -> g_h1 (fp16 MMA) --------
#define KST 64
#define SST 72   // halves per row: conflict-free frag loads

__device__ __forceinline__ void mma_f16(float* c, const uint32_t* a,
                                        const uint32_t* b) {
    asm volatile(
        "mma.sync.aligned.m16n8k16.row.col.f32.f16.f16.f32 "
        "{%0,%1,%2,%3}, {%4,%5,%6,%7}, {%8,%9}, {%0,%1,%2,%3};"
        : "+f"(c[0]), "+f"(c[1]), "+f"(c[2]), "+f"(c[3])
        : "r"(a[0]), "r"(a[1]), "r"(a[2]), "r"(a[3]), "r"(b[0]), "r"(b[1]));
}

__global__ void __launch_bounds__(256) k_gemm_tc() {
    __shared__ __half sA[128 * SST];   // A tile: [row][k]  (128 x 64)
    __shared__ __half sB[128 * SST];   // B^T tile: [n][k]  (128 x 64)

    int t = threadIdx.x;
    int warp = t >> 5, lane = t & 31;
    int wm = warp >> 2, wn = warp & 3;
    int group = lane >> 2, tg = lane & 3;
    int i0 = blockIdx.x * 128;

    float acc[4][4][4];
    #pragma unroll
    for (int a = 0; a < 4; a++)
        #pragma unroll
        for (int b = 0; b < 4; b++)
            #pragma unroll
            for (int c = 0; c < 4; c++) acc[a][b][c] = 0.f;

    for (int k0 = 0; k0 < DIM; k0 += KST) {
        #pragma unroll
        for (int l = 0; l < 4; l++) {
            int q = t + l * 256;          // 0..1023
            int rrow = q >> 3;
            int c8 = (q & 7) * 8;
            uint4 v = make_uint4(0u, 0u, 0u, 0u);
            int gr = i0 + rrow;
            if (gr < N_NODES)
                v = *reinterpret_cast<const uint4*>(
                        &g_h2[(size_t)gr * DIM + k0 + c8]);
            *reinterpret_cast<uint4*>(&sA[rrow * SST + c8]) = v;
        }
        #pragma unroll
        for (int l = 0; l < 4; l++) {
            int q = t + l * 256;
            int nrow = q >> 3;
            int c8 = (q & 7) * 8;
            *reinterpret_cast<uint4*>(&sB[nrow * SST + c8]) =
                *reinterpret_cast<const uint4*>(&g_BhT[nrow * DIM + k0 + c8]);
        }
        __syncthreads();

        #pragma unroll
        for (int ks = 0; ks < KST / 16; ks++) {
            int kb = ks * 16;
            uint32_t bf[4][2];
            #pragma unroll
            for (int nn = 0; nn < 4; nn++) {
                int n0 = wn * 32 + nn * 8 + group;
                bf[nn][0] = *reinterpret_cast<const uint32_t*>(
                                &sB[n0 * SST + kb + tg * 2]);
                bf[nn][1] = *reinterpret_cast<const uint32_t*>(
                                &sB[n0 * SST + kb + 8 + tg * 2]);
            }
            uint32_t af[4][4];
            #pragma unroll
            for (int mm = 0; mm < 4; mm++) {
                int r0 = wm * 64 + mm * 16 + group;
                af[mm][0] = *reinterpret_cast<const uint32_t*>(
                                &sA[r0 * SST + kb + tg * 2]);
                af[mm][1] = *reinterpret_cast<const uint32_t*>(
                                &sA[(r0 + 8) * SST + kb + tg * 2]);
                af[mm][2] = *reinterpret_cast<const uint32_t*>(
                                &sA[r0 * SST + kb + 8 + tg * 2]);
                af[mm][3] = *reinterpret_cast<const uint32_t*>(
                                &sA[(r0 + 8) * SST + kb + 8 + tg * 2]);
            }
            #pragma unroll
            for (int mm = 0; mm < 4; mm++)
                #pragma unroll
                for (int nn = 0; nn < 4; nn++)
                    mma_f16(acc[mm][nn], af[mm], bf[nn]);
        }
        __syncthreads();
    }

    #pragma unroll
    for (int mm = 0; mm < 4; mm++) {
        #pragma unroll
        for (int nn = 0; nn < 4; nn++) {
            int colb = wn * 32 + nn * 8 + tg * 2;
            #pragma unroll
            for (int half = 0; half < 2; half++) {
                int rr = i0 + wm * 64 + mm * 16 + group + half * 8;
                if (rr < N_NODES) {
                    float v0 = acc[mm][nn][half * 2 + 0];
                    float v1 = acc[mm][nn][half * 2 + 1];
                    v0 = (v0 > 0.f) ? v0 : 0.01f * v0;
                    v1 = (v1 > 0.f) ? v1 : 0.01f * v1;
                    __half2 hv = __floats2half2_rn(v0, v1);
                    *reinterpret_cast<__half2*>(
                        &g_h1[(size_t)rr * DIM + colb]) = hv;
                }
            }
        }
    }
}

// ---------------- out = g_z @ W2 (fp32) ----------------
__global__ void k_out(const float* __restrict__ W2, float* __restrict__ out) {
    __shared__ float sz[DIM];
    int g = blockIdx.x;
    int j = threadIdx.x;
    sz[j] = g_z[g * DIM + j];
    __syncthreads();
    float acc = 0.f;
    #pragma unroll 8
    for (int k = 0; k < DIM; k++)
        acc += sz[k] * W2[k * DIM + j];
    out[g * DIM + j] = acc;
}

// ---------------- launch (fork-join: prep overlaps CSR build) ---------
extern "C" void kernel_launch(void* const* d_in, const int* in_sizes, int n_in,
                              void* d_out, int out_size) {
    const float* x     = (const float*)d_in[0];
    const int*   ei    = (const int*)d_in[1];
    const int*   batch = (const int*)d_in[2];
    const float* W0    = (const float*)d_in[3];
    const float* W1    = (const float*)d_in[4];
    const float* W2    = (const float*)d_in[5];
    float* out = (float*)d_out;

    const int* row = ei;
    const int* col = ei + N_EDGES;

    cudaStream_t s2;
    cudaStreamCreateWithFlags(&s2, cudaStreamNonBlocking);
    cudaEvent_t eFork, eJoin;
    cudaEventCreateWithFlags(&eFork, cudaEventDisableTiming);
    cudaEventCreateWithFlags(&eJoin, cudaEventDisableTiming);

    cudaEventRecord(eFork, 0);
    cudaStreamWaitEvent(s2, eFork, 0);

    // branch B (s2): x -> fp16 + W12^T fp16 + zero z
    k_prep<<<PBLOCKS + WBLOCKS, 256, 0, s2>>>(x, W0, W1);
    cudaEventRecord(eJoin, s2);

    // branch A (stream 0): CSR build
    k_zero<<<(N_NODES + 255) / 256, 256>>>();
    k_deg<<<(N_EDGES + 255) / 256, 256>>>(col);
    k_scan1<<<NB, 256>>>();
    k_scan3<<<NB, SCAN_CHUNK>>>();
    k_scatter<<<(N_EDGES + 255) / 256, 256>>>(row, col);

    cudaStreamWaitEvent(0, eJoin, 0);

    k_cprop<0><<<CPBLOCKS, 256>>>(batch);            // y1 = Â x      (fp16)
    k_cprop<1><<<CPBLOCKS, 256>>>(batch);            // y2 = Â y1     (fp16)
    k_gemm_tc<<<(N_NODES + 127) / 128, 256>>>();     // y3 = leaky(y2@W12)
    k_cprop<2><<<CPBLOCKS, 256>>>(batch);            // z = P Â y3    (fp32)
    k_out<<<N_GRAPHS, DIM>>>(W2, out);
}